// round 4
// baseline (speedup 1.0000x reference)
#include <cuda_runtime.h>
#include <cuda_bf16.h>

// RBFEmbedding: out[b,i,d] = token_emb[an[b,i],d] + proj_b[d]
//                          + (1/N) * sum_j sum_k exp(-((d_ij - c_k)/w)^2) * W[k,d]
// B=16, N=512, K=50, D=256. Centers c_k = k*delta, delta = 12/49, w = 2*delta.
//
// Packed double-step recurrence over an even-aligned 14-center window:
//   (rbf_m, rbf_{m+1}) *= (g_m g_{m+1}, g_{m+1} g_{m+2}),  G-pair *= (e^-2, e^-2)
// Accumulators are float2 in smem, [kk][tid] layout -> conflict-free LDS.64/STS.64.
// 256 threads/block (8 warps) to hide FMUL-chain + LDS latency (R2 showed
// issue=44.8% @ occ=21%). sacc2 (51.2 KB) lives in DYNAMIC smem because the
// static limit is 48 KB; opt-in via cudaFuncSetAttribute.

#define THREADS 256
#define R 16           // rows (i) per block
#define JG 16          // j-groups (THREADS / R)
#define JLEN 32        // 512 / JG
#define NS 50
#define KK 25          // 64-bit accumulator slots (2 k each)
#define WIN2 7         // 7 double-steps = 14-center window

typedef unsigned long long ull;

#define SACC_BYTES (KK * THREADS * 8)   // 51200

__device__ __forceinline__ ull pack2(float lo, float hi) {
    ull r; asm("mov.b64 %0, {%1, %2};" : "=l"(r) : "f"(lo), "f"(hi)); return r;
}
__device__ __forceinline__ void unpack2(ull v, float& lo, float& hi) {
    asm("mov.b64 {%0, %1}, %2;" : "=f"(lo), "=f"(hi) : "l"(v));
}
__device__ __forceinline__ ull add2(ull a, ull b) {
    ull r; asm("add.rn.f32x2 %0, %1, %2;" : "=l"(r) : "l"(a), "l"(b)); return r;
}
__device__ __forceinline__ ull mul2(ull a, ull b) {
    ull r; asm("mul.rn.f32x2 %0, %1, %2;" : "=l"(r) : "l"(a), "l"(b)); return r;
}
__device__ __forceinline__ ull fma2(ull a, ull b, ull c) {
    ull r; asm("fma.rn.f32x2 %0, %1, %2, %3;" : "=l"(r) : "l"(a), "l"(b), "l"(c)); return r;
}

__global__ __launch_bounds__(THREADS)
void rbf_embed_kernel(const int* __restrict__ an,
                      const float* __restrict__ pos,
                      const float* __restrict__ tok,
                      const float* __restrict__ W,
                      const float* __restrict__ bias,
                      float* __restrict__ out)
{
    extern __shared__ ull sacc2[];        // [KK][THREADS], 51.2 KB dynamic
    __shared__ float sx[512], sy[512], sz[512];
    __shared__ ull  rbfm2[NS][R / 2];     // rbf means, float2 over ii-pairs
    __shared__ int  an_s[R];

    const int tid = threadIdx.x;
    const int b   = blockIdx.y;
    const int i0  = blockIdx.x * R;

    // ---- positions -> smem (SoA) ----
    const float* pb = pos + (size_t)b * 512 * 3;
    for (int j = tid; j < 512; j += THREADS) {
        sx[j] = pb[j * 3 + 0];
        sy[j] = pb[j * 3 + 1];
        sz[j] = pb[j * 3 + 2];
    }
    if (tid < R) an_s[tid] = an[b * 512 + i0 + tid];
    #pragma unroll
    for (int kk = 0; kk < KK; ++kk) sacc2[kk * THREADS + tid] = 0ULL;
    __syncthreads();

    const int r  = tid & (R - 1);
    const int jg = tid >> 4;             // 0..15
    const float xi = sx[i0 + r], yi = sy[i0 + r], zi = sz[i0 + r];

    const float INV_DELTA = 49.0f / 12.0f;
    const float MAGIC     = 12582912.0f;                 // 1.5*2^23
    const float SQL2E     = 1.2011224087864498f;         // sqrt(log2 e)
    const float L2E       = 1.4426950408889634f;
    const float NQL2E     = -0.25f * 1.4426950408889634f;
    const float BETA      = 0.60653065971263342f;        // e^-1/2
    const float BETA2     = 0.36787944117144233f;        // e^-1
    const ull   B4        = pack2(0.13533528323661270f, 0.13533528323661270f); // e^-2

    const int jbase = jg * JLEN;
    #pragma unroll 2
    for (int jj = 0; jj < JLEN; ++jj) {
        const int j = jbase + jj;
        float dx = xi - sx[j];
        float dy = yi - sy[j];
        float dz = zi - sz[j];
        float dd = fmaf(dx, dx, fmaf(dy, dy, fmaf(dz, dz, 1e-8f)));
        float d;  asm("sqrt.approx.f32 %0, %1;" : "=f"(d) : "f"(dd));
        d = fminf(d, 16.0f);

        float t  = d * INV_DELTA;                      // d/delta in [0, 65.4]
        float hf = fmaf(t, 0.5f, -3.5f);               // (t-7)/2
        float hr = __fadd_rn(__fadd_rn(hf, MAGIC), -MAGIC);   // rint
        hr = fminf(fmaxf(hr, 0.0f), 18.0f);            // kk0 in [0,18], k0 = 2*hr
        const int kk0 = (int)hr;
        float x0 = fmaf(t, 0.5f, -hr);                 // (d - k0*delta)/w

        // rr0 = exp(-x0^2); g0 = exp(x0 - 1/4)
        float u  = x0 * SQL2E;
        float a0 = -(u * u);
        float rr0; asm("ex2.approx.f32 %0, %1;" : "=f"(rr0) : "f"(a0));
        float ga = fmaf(x0, L2E, NQL2E);
        float g0; asm("ex2.approx.f32 %0, %1;" : "=f"(g0) : "f"(ga));

        float g0sq = g0 * g0;
        float gA   = g0sq * BETA;        // g0*g1
        float gB   = gA * BETA2;         // g1*g2
        ull Gp  = pack2(gA, gB);
        ull rrp = pack2(rr0, rr0 * g0);  // (rbf_0, rbf_1)

        ull* ap = &sacc2[kk0 * THREADS + tid];
        #pragma unroll
        for (int tt = 0; tt < WIN2; ++tt) {
            ap[tt * THREADS] = add2(ap[tt * THREADS], rrp);
            rrp = mul2(rrp, Gp);
            Gp  = mul2(Gp, B4);
        }
    }
    __syncthreads();

    // ---- reduce JG partials per (k, ii), fold in 1/N ----
    for (int idx = tid; idx < NS * R; idx += THREADS) {
        const int k  = idx >> 4;
        const int ii = idx & (R - 1);
        const float* sf = (const float*)&sacc2[(k >> 1) * THREADS];
        const int par = (k & 1);
        float s = 0.0f;
        #pragma unroll
        for (int g = 0; g < JG; ++g)
            s += sf[(g * R + ii) * 2 + par];
        ((float*)rbfm2)[k * R + ii] = s * (1.0f / 512.0f);
    }
    __syncthreads();

    // ---- epilogue: [16 x 50] @ [50 x 256] + bias + token gather ----
    // thread owns column d0 = tid; acc packed over ii-pairs (8 x float2).
    {
        const int d0 = tid;
        const float bd = __ldg(&bias[d0]);
        ull acc[8];
        #pragma unroll
        for (int p = 0; p < 8; ++p) {
            acc[p] = pack2(bd + __ldg(&tok[an_s[2 * p] * 256 + d0]),
                           bd + __ldg(&tok[an_s[2 * p + 1] * 256 + d0]));
        }
        #pragma unroll 2
        for (int k = 0; k < NS; ++k) {
            const float w = __ldg(&W[k * 256 + d0]);
            const ull wp = pack2(w, w);
            const ull* rp = rbfm2[k];
            #pragma unroll
            for (int p = 0; p < 8; ++p)
                acc[p] = fma2(rp[p], wp, acc[p]);   // rp[p]: broadcast LDS.64
        }
        float* op = out + ((size_t)(b * 512 + i0)) * 256 + d0;
        #pragma unroll
        for (int p = 0; p < 8; ++p) {
            float lo, hi;
            unpack2(acc[p], lo, hi);
            op[(2 * p) * 256]     = lo;
            op[(2 * p + 1) * 256] = hi;
        }
    }
}

extern "C" void kernel_launch(void* const* d_in, const int* in_sizes, int n_in,
                              void* d_out, int out_size)
{
    const int*   an   = (const int*)  d_in[0];   // [B,512] int32
    const float* pos  = (const float*)d_in[1];   // [B,512,3] f32
    const float* tok  = (const float*)d_in[2];   // [100,256] f32
    const float* W    = (const float*)d_in[3];   // [50,256]  f32
    const float* bias = (const float*)d_in[4];   // [256]     f32

    const int B = in_sizes[0] / 512;             // 16
    dim3 grid(512 / R, B);

    static bool attr_set = false;
    if (!attr_set) {
        cudaFuncSetAttribute(rbf_embed_kernel,
                             cudaFuncAttributeMaxDynamicSharedMemorySize,
                             SACC_BYTES);
        attr_set = true;
    }
    rbf_embed_kernel<<<grid, THREADS, SACC_BYTES>>>(an, pos, tok, W, bias,
                                                    (float*)d_out);
}

// round 5
// speedup vs baseline: 1.3458x; 1.3458x over previous
#include <cuda_runtime.h>
#include <cuda_bf16.h>

// RBFEmbedding: out[b,i,d] = token_emb[an[b,i],d] + proj_b[d]
//                          + (1/N) * sum_j sum_k exp(-((d_ij - c_k)/w)^2) * W[k,d]
// B=16, N=512, K=50, D=256. Centers c_k = k*delta, delta = 12/49, w = 2*delta.
//
// Packed double-step recurrence over an even-aligned 14-center window:
//   (rbf_m, rbf_{m+1}) *= (g_m g_{m+1}, g_{m+1} g_{m+2}),  G-pair *= (e^-2, e^-2)
// Accumulators are float2 in STATIC smem, [kk][tid] -> conflict-free LDS/STS.64.
// R4->R5: keep the proven 128-thread code shape (R2 ran 33.6us with a 78-reg
// pipelined schedule); fix the grid-limited occupancy (21%) by halving rows
// per block (R=8 -> 1024 blocks, ~6 resident blocks x 4 warps = 37% occ).

#define THREADS 128
#define R 8            // rows (i) per block
#define JG 16          // j-groups (THREADS / R)
#define JLEN 32        // 512 / JG
#define NS 50
#define KK 25          // 64-bit accumulator slots (2 k each)
#define WIN2 7         // 7 double-steps = 14-center window

typedef unsigned long long ull;

__device__ __forceinline__ ull pack2(float lo, float hi) {
    ull r; asm("mov.b64 %0, {%1, %2};" : "=l"(r) : "f"(lo), "f"(hi)); return r;
}
__device__ __forceinline__ void unpack2(ull v, float& lo, float& hi) {
    asm("mov.b64 {%0, %1}, %2;" : "=f"(lo), "=f"(hi) : "l"(v));
}
__device__ __forceinline__ ull add2(ull a, ull b) {
    ull r; asm("add.rn.f32x2 %0, %1, %2;" : "=l"(r) : "l"(a), "l"(b)); return r;
}
__device__ __forceinline__ ull mul2(ull a, ull b) {
    ull r; asm("mul.rn.f32x2 %0, %1, %2;" : "=l"(r) : "l"(a), "l"(b)); return r;
}
__device__ __forceinline__ ull fma2(ull a, ull b, ull c) {
    ull r; asm("fma.rn.f32x2 %0, %1, %2, %3;" : "=l"(r) : "l"(a), "l"(b), "l"(c)); return r;
}

__global__ __launch_bounds__(THREADS)
void rbf_embed_kernel(const int* __restrict__ an,
                      const float* __restrict__ pos,
                      const float* __restrict__ tok,
                      const float* __restrict__ W,
                      const float* __restrict__ bias,
                      float* __restrict__ out)
{
    __shared__ float sx[512], sy[512], sz[512];   // 6 KB
    __shared__ ull  sacc2[KK][THREADS];           // 25.6 KB, [kk][thread]
    __shared__ ull  rbfm2[NS][R / 2];             // 1.6 KB
    __shared__ int  an_s[R];

    const int tid = threadIdx.x;
    const int b   = blockIdx.y;
    const int i0  = blockIdx.x * R;

    // ---- positions -> smem (SoA) ----
    const float* pb = pos + (size_t)b * 512 * 3;
    for (int j = tid; j < 512; j += THREADS) {
        sx[j] = pb[j * 3 + 0];
        sy[j] = pb[j * 3 + 1];
        sz[j] = pb[j * 3 + 2];
    }
    if (tid < R) an_s[tid] = an[b * 512 + i0 + tid];
    #pragma unroll
    for (int kk = 0; kk < KK; ++kk) sacc2[kk][tid] = 0ULL;
    __syncthreads();

    const int r  = tid & (R - 1);
    const int jg = tid >> 3;             // 0..15
    const float xi = sx[i0 + r], yi = sy[i0 + r], zi = sz[i0 + r];

    const float INV_DELTA = 49.0f / 12.0f;
    const float MAGIC     = 12582912.0f;                 // 1.5*2^23
    const float SQL2E     = 1.2011224087864498f;         // sqrt(log2 e)
    const float L2E       = 1.4426950408889634f;
    const float NQL2E     = -0.25f * 1.4426950408889634f;
    const float BETA      = 0.60653065971263342f;        // e^-1/2
    const float BETA2     = 0.36787944117144233f;        // e^-1
    const ull   B4        = pack2(0.13533528323661270f, 0.13533528323661270f); // e^-2

    const int jbase = jg * JLEN;
    #pragma unroll 2
    for (int jj = 0; jj < JLEN; ++jj) {
        const int j = jbase + jj;
        float dx = xi - sx[j];
        float dy = yi - sy[j];
        float dz = zi - sz[j];
        float dd = fmaf(dx, dx, fmaf(dy, dy, fmaf(dz, dz, 1e-8f)));
        float d;  asm("sqrt.approx.f32 %0, %1;" : "=f"(d) : "f"(dd));
        d = fminf(d, 16.0f);

        float t  = d * INV_DELTA;                      // d/delta in [0, 65.4]
        float hf = fmaf(t, 0.5f, -3.5f);               // (t-7)/2
        float hr = __fadd_rn(__fadd_rn(hf, MAGIC), -MAGIC);   // rint
        hr = fminf(fmaxf(hr, 0.0f), 18.0f);            // kk0 in [0,18], k0 = 2*hr
        const int kk0 = (int)hr;
        float x0 = fmaf(t, 0.5f, -hr);                 // (d - k0*delta)/w

        // rr0 = exp(-x0^2); g0 = exp(x0 - 1/4)
        float u  = x0 * SQL2E;
        float a0 = -(u * u);
        float rr0; asm("ex2.approx.f32 %0, %1;" : "=f"(rr0) : "f"(a0));
        float ga = fmaf(x0, L2E, NQL2E);
        float g0; asm("ex2.approx.f32 %0, %1;" : "=f"(g0) : "f"(ga));

        float g0sq = g0 * g0;
        float gA   = g0sq * BETA;        // g0*g1
        float gB   = gA * BETA2;         // g1*g2
        ull Gp  = pack2(gA, gB);
        ull rrp = pack2(rr0, rr0 * g0);  // (rbf_0, rbf_1)

        ull* ap = &sacc2[kk0][tid];
        #pragma unroll
        for (int tt = 0; tt < WIN2; ++tt) {
            ap[tt * THREADS] = add2(ap[tt * THREADS], rrp);
            rrp = mul2(rrp, Gp);
            Gp  = mul2(Gp, B4);
        }
    }
    __syncthreads();

    // ---- reduce JG partials per (k, ii), fold in 1/N ----
    for (int idx = tid; idx < NS * R; idx += THREADS) {
        const int k  = idx >> 3;            // idx / R
        const int ii = idx & (R - 1);
        const float* sf = (const float*)&sacc2[k >> 1][0];
        const int par = (k & 1);
        float s = 0.0f;
        #pragma unroll
        for (int g = 0; g < JG; ++g)
            s += sf[(g * R + ii) * 2 + par];
        ((float*)rbfm2)[k * R + ii] = s * (1.0f / 512.0f);
    }
    __syncthreads();

    // ---- epilogue: [8 x 50] @ [50 x 256] + bias + token gather ----
    // thread owns columns (d0, d0+128); acc packed over ii-pairs (4 x float2 each).
    {
        const int d0 = tid;
        const float bd0 = __ldg(&bias[d0]);
        const float bd1 = __ldg(&bias[d0 + 128]);
        ull accA[4], accB[4];
        #pragma unroll
        for (int p = 0; p < 4; ++p) {
            const int ta = an_s[2 * p] * 256, tb = an_s[2 * p + 1] * 256;
            accA[p] = pack2(bd0 + __ldg(&tok[ta + d0]),       bd0 + __ldg(&tok[tb + d0]));
            accB[p] = pack2(bd1 + __ldg(&tok[ta + d0 + 128]), bd1 + __ldg(&tok[tb + d0 + 128]));
        }
        #pragma unroll 2
        for (int k = 0; k < NS; ++k) {
            const float wa = __ldg(&W[k * 256 + d0]);
            const float wb = __ldg(&W[k * 256 + d0 + 128]);
            const ull wpa = pack2(wa, wa);
            const ull wpb = pack2(wb, wb);
            const ull* rp = rbfm2[k];
            #pragma unroll
            for (int p = 0; p < 4; ++p) {
                const ull rv = rp[p];      // warp-uniform broadcast LDS.64
                accA[p] = fma2(rv, wpa, accA[p]);
                accB[p] = fma2(rv, wpb, accB[p]);
            }
        }
        float* op = out + ((size_t)(b * 512 + i0)) * 256 + d0;
        #pragma unroll
        for (int p = 0; p < 4; ++p) {
            float lo, hi;
            unpack2(accA[p], lo, hi);
            op[(2 * p) * 256]       = lo;
            op[(2 * p + 1) * 256]   = hi;
            unpack2(accB[p], lo, hi);
            op[(2 * p) * 256 + 128]     = lo;
            op[(2 * p + 1) * 256 + 128] = hi;
        }
    }
}

extern "C" void kernel_launch(void* const* d_in, const int* in_sizes, int n_in,
                              void* d_out, int out_size)
{
    const int*   an   = (const int*)  d_in[0];   // [B,512] int32
    const float* pos  = (const float*)d_in[1];   // [B,512,3] f32
    const float* tok  = (const float*)d_in[2];   // [100,256] f32
    const float* W    = (const float*)d_in[3];   // [50,256]  f32
    const float* bias = (const float*)d_in[4];   // [256]     f32

    const int B = in_sizes[0] / 512;             // 16
    dim3 grid(512 / R, B);                       // 64 x 16 = 1024 blocks
    rbf_embed_kernel<<<grid, THREADS>>>(an, pos, tok, W, bias, (float*)d_out);
}

// round 6
// speedup vs baseline: 1.3880x; 1.0313x over previous
#include <cuda_runtime.h>
#include <cuda_bf16.h>

// RBFEmbedding: out[b,i,d] = token_emb[an[b,i],d] + proj_b[d]
//                          + (1/N) * sum_j sum_k exp(-((d_ij - c_k)/w)^2) * W[k,d]
// B=16, N=512, K=50, D=256. Centers c_k = k*delta, delta = 12/49, w = 2*delta.
//
// Packed double-step recurrence over an even-aligned 14-center window:
//   (rbf_m, rbf_{m+1}) *= (g_m g_{m+1}, g_{m+1} g_{m+2}),  G-pair *= (e^-2, e^-2)
// Accumulators float2 in static smem, [kk][tid] -> conflict-free LDS/STS.64.
//
// R5->R6: (1) hand-hoisted window loads (7 independent LDS.64 issued together,
// then add+store) so the 29-cyc LDS latency is pipelined regardless of ptxas's
// register heuristic; (2) __launch_bounds__(128,1) so ptxas doesn't clamp regs
// (R4/R5 regressions were low-reg serialized schedules); (3) keep R=8 ->
// 1024 blocks for ~31-43% occupancy.

#define THREADS 128
#define R 8            // rows (i) per block
#define JG 16          // j-groups (THREADS / R)
#define JLEN 32        // 512 / JG
#define NS 50
#define KK 25          // 64-bit accumulator slots (2 k each)
#define WIN2 7         // 7 double-steps = 14-center window

typedef unsigned long long ull;

__device__ __forceinline__ ull pack2(float lo, float hi) {
    ull r; asm("mov.b64 %0, {%1, %2};" : "=l"(r) : "f"(lo), "f"(hi)); return r;
}
__device__ __forceinline__ void unpack2(ull v, float& lo, float& hi) {
    asm("mov.b64 {%0, %1}, %2;" : "=f"(lo), "=f"(hi) : "l"(v));
}
__device__ __forceinline__ ull add2(ull a, ull b) {
    ull r; asm("add.rn.f32x2 %0, %1, %2;" : "=l"(r) : "l"(a), "l"(b)); return r;
}
__device__ __forceinline__ ull mul2(ull a, ull b) {
    ull r; asm("mul.rn.f32x2 %0, %1, %2;" : "=l"(r) : "l"(a), "l"(b)); return r;
}
__device__ __forceinline__ ull fma2(ull a, ull b, ull c) {
    ull r; asm("fma.rn.f32x2 %0, %1, %2, %3;" : "=l"(r) : "l"(a), "l"(b), "l"(c)); return r;
}

__global__ __launch_bounds__(THREADS, 1)
void rbf_embed_kernel(const int* __restrict__ an,
                      const float* __restrict__ pos,
                      const float* __restrict__ tok,
                      const float* __restrict__ W,
                      const float* __restrict__ bias,
                      float* __restrict__ out)
{
    __shared__ float sx[512], sy[512], sz[512];   // 6 KB
    __shared__ ull  sacc2[KK][THREADS];           // 25.6 KB, [kk][thread]
    __shared__ ull  rbfm2[NS][R / 2];             // 1.6 KB
    __shared__ int  an_s[R];

    const int tid = threadIdx.x;
    const int b   = blockIdx.y;
    const int i0  = blockIdx.x * R;

    // ---- positions -> smem (SoA) ----
    const float* pb = pos + (size_t)b * 512 * 3;
    for (int j = tid; j < 512; j += THREADS) {
        sx[j] = pb[j * 3 + 0];
        sy[j] = pb[j * 3 + 1];
        sz[j] = pb[j * 3 + 2];
    }
    if (tid < R) an_s[tid] = an[b * 512 + i0 + tid];
    #pragma unroll
    for (int kk = 0; kk < KK; ++kk) sacc2[kk][tid] = 0ULL;
    __syncthreads();

    const int r  = tid & (R - 1);
    const int jg = tid >> 3;             // 0..15
    const float xi = sx[i0 + r], yi = sy[i0 + r], zi = sz[i0 + r];

    const float INV_DELTA = 49.0f / 12.0f;
    const float MAGIC     = 12582912.0f;                 // 1.5*2^23
    const float SQL2E     = 1.2011224087864498f;         // sqrt(log2 e)
    const float L2E       = 1.4426950408889634f;
    const float NQL2E     = -0.25f * 1.4426950408889634f;
    const float BETA      = 0.60653065971263342f;        // e^-1/2
    const float BETA2     = 0.36787944117144233f;        // e^-1
    const ull   B4        = pack2(0.13533528323661270f, 0.13533528323661270f); // e^-2

    const int jbase = jg * JLEN;
    #pragma unroll 2
    for (int jj = 0; jj < JLEN; ++jj) {
        const int j = jbase + jj;
        float dx = xi - sx[j];
        float dy = yi - sy[j];
        float dz = zi - sz[j];
        float dd = fmaf(dx, dx, fmaf(dy, dy, fmaf(dz, dz, 1e-8f)));
        float d;  asm("sqrt.approx.f32 %0, %1;" : "=f"(d) : "f"(dd));
        d = fminf(d, 16.0f);

        float t  = d * INV_DELTA;                      // d/delta in [0, 65.4]
        float hf = fmaf(t, 0.5f, -3.5f);               // (t-7)/2
        float hr = __fadd_rn(__fadd_rn(hf, MAGIC), -MAGIC);   // rint
        hr = fminf(fmaxf(hr, 0.0f), 18.0f);            // kk0 in [0,18], k0 = 2*hr
        const int kk0 = (int)hr;
        float x0 = fmaf(t, 0.5f, -hr);                 // (d - k0*delta)/w

        // rr0 = exp(-x0^2); g0 = exp(x0 - 1/4)
        float u  = x0 * SQL2E;
        float a0 = -(u * u);
        float rr0; asm("ex2.approx.f32 %0, %1;" : "=f"(rr0) : "f"(a0));
        float ga = fmaf(x0, L2E, NQL2E);
        float g0; asm("ex2.approx.f32 %0, %1;" : "=f"(g0) : "f"(ga));

        float g0sq = g0 * g0;
        float gA   = g0sq * BETA;        // g0*g1
        float gB   = gA * BETA2;         // g1*g2
        ull Gp  = pack2(gA, gB);
        ull rrp = pack2(rr0, rr0 * g0);  // (rbf_0, rbf_1)

        ull* ap = &sacc2[kk0][tid];

        // hoisted loads: 7 independent LDS.64, latency overlapped
        ull v[WIN2];
        #pragma unroll
        for (int tt = 0; tt < WIN2; ++tt)
            v[tt] = ap[tt * THREADS];
        // add + store + advance recurrence
        #pragma unroll
        for (int tt = 0; tt < WIN2; ++tt) {
            ap[tt * THREADS] = add2(v[tt], rrp);
            rrp = mul2(rrp, Gp);
            Gp  = mul2(Gp, B4);
        }
    }
    __syncthreads();

    // ---- reduce JG partials per (k, ii), fold in 1/N ----
    for (int idx = tid; idx < NS * R; idx += THREADS) {
        const int k  = idx >> 3;            // idx / R
        const int ii = idx & (R - 1);
        const float* sf = (const float*)&sacc2[k >> 1][0];
        const int par = (k & 1);
        float s = 0.0f;
        #pragma unroll
        for (int g = 0; g < JG; ++g)
            s += sf[(g * R + ii) * 2 + par];
        ((float*)rbfm2)[k * R + ii] = s * (1.0f / 512.0f);
    }
    __syncthreads();

    // ---- epilogue: [8 x 50] @ [50 x 256] + bias + token gather ----
    // thread owns columns (d0, d0+128); acc packed over ii-pairs (4 x float2 each).
    {
        const int d0 = tid;
        const float bd0 = __ldg(&bias[d0]);
        const float bd1 = __ldg(&bias[d0 + 128]);
        ull accA[4], accB[4];
        #pragma unroll
        for (int p = 0; p < 4; ++p) {
            const int ta = an_s[2 * p] * 256, tb = an_s[2 * p + 1] * 256;
            accA[p] = pack2(bd0 + __ldg(&tok[ta + d0]),       bd0 + __ldg(&tok[tb + d0]));
            accB[p] = pack2(bd1 + __ldg(&tok[ta + d0 + 128]), bd1 + __ldg(&tok[tb + d0 + 128]));
        }
        #pragma unroll 2
        for (int k = 0; k < NS; ++k) {
            const float wa = __ldg(&W[k * 256 + d0]);
            const float wb = __ldg(&W[k * 256 + d0 + 128]);
            const ull wpa = pack2(wa, wa);
            const ull wpb = pack2(wb, wb);
            const ull* rp = rbfm2[k];
            #pragma unroll
            for (int p = 0; p < 4; ++p) {
                const ull rv = rp[p];      // warp-uniform broadcast LDS.64
                accA[p] = fma2(rv, wpa, accA[p]);
                accB[p] = fma2(rv, wpb, accB[p]);
            }
        }
        float* op = out + ((size_t)(b * 512 + i0)) * 256 + d0;
        #pragma unroll
        for (int p = 0; p < 4; ++p) {
            float lo, hi;
            unpack2(accA[p], lo, hi);
            op[(2 * p) * 256]       = lo;
            op[(2 * p + 1) * 256]   = hi;
            unpack2(accB[p], lo, hi);
            op[(2 * p) * 256 + 128]     = lo;
            op[(2 * p + 1) * 256 + 128] = hi;
        }
    }
}

extern "C" void kernel_launch(void* const* d_in, const int* in_sizes, int n_in,
                              void* d_out, int out_size)
{
    const int*   an   = (const int*)  d_in[0];   // [B,512] int32
    const float* pos  = (const float*)d_in[1];   // [B,512,3] f32
    const float* tok  = (const float*)d_in[2];   // [100,256] f32
    const float* W    = (const float*)d_in[3];   // [50,256]  f32
    const float* bias = (const float*)d_in[4];   // [256]     f32

    const int B = in_sizes[0] / 512;             // 16
    dim3 grid(512 / R, B);                       // 64 x 16 = 1024 blocks
    rbf_embed_kernel<<<grid, THREADS>>>(an, pos, tok, W, bias, (float*)d_out);
}

// round 7
// speedup vs baseline: 1.5882x; 1.1443x over previous
#include <cuda_runtime.h>
#include <cuda_bf16.h>

// RBFEmbedding: out[b,i,d] = token_emb[an[b,i],d] + proj_b[d]
//                          + (1/N) * sum_j sum_k exp(-((d_ij - c_k)/w)^2) * W[k,d]
// B=16, N=512, K=50, D=256. Centers c_k = k*delta, delta = 12/49, w = 2*delta.
//
// Packed double-step recurrence over an even-aligned 14-center window:
//   (rbf_m, rbf_{m+1}) *= (g_m g_{m+1}, g_{m+1} g_{m+2}),  G-pair *= (e^-2, e^-2)
// Accumulators float2 in static smem, [kk][tid] -> conflict-free LDS/STS.64.
//
// R7: exact R2 geometry (R=16, THREADS=128, JG=8, JLEN=64 -- the only config
// ptxas pipelines well, 78 regs / 33.6us) + EXPLICIT 2-stage software pipeline:
// params for j+1 (sqrt + 2x ex2 + FMAs, long latency, independent) are computed
// before the window RMW of j (LDS/STS + serial mul chain), so each phase's
// stalls are filled by the other phase regardless of scheduler heuristics.

#define THREADS 128
#define R 16           // rows (i) per block
#define JG 8           // j-groups (THREADS / R)
#define JLEN 64        // 512 / JG
#define NS 50
#define KK 25          // 64-bit accumulator slots (2 k each)
#define WIN2 7         // 7 double-steps = 14-center window

typedef unsigned long long ull;

__device__ __forceinline__ ull pack2(float lo, float hi) {
    ull r; asm("mov.b64 %0, {%1, %2};" : "=l"(r) : "f"(lo), "f"(hi)); return r;
}
__device__ __forceinline__ void unpack2(ull v, float& lo, float& hi) {
    asm("mov.b64 {%0, %1}, %2;" : "=f"(lo), "=f"(hi) : "l"(v));
}
__device__ __forceinline__ ull add2(ull a, ull b) {
    ull r; asm("add.rn.f32x2 %0, %1, %2;" : "=l"(r) : "l"(a), "l"(b)); return r;
}
__device__ __forceinline__ ull mul2(ull a, ull b) {
    ull r; asm("mul.rn.f32x2 %0, %1, %2;" : "=l"(r) : "l"(a), "l"(b)); return r;
}
__device__ __forceinline__ ull fma2(ull a, ull b, ull c) {
    ull r; asm("fma.rn.f32x2 %0, %1, %2, %3;" : "=l"(r) : "l"(a), "l"(b), "l"(c)); return r;
}

// distance -> (window slot kk0, packed rbf pair rrp, packed ratio pair Gp)
__device__ __forceinline__ void pair_params(
    float xi, float yi, float zi,
    const float* __restrict__ sx, const float* __restrict__ sy,
    const float* __restrict__ sz, int j,
    int& kk0, ull& rrp, ull& Gp)
{
    const float INV_DELTA = 49.0f / 12.0f;
    const float MAGIC     = 12582912.0f;                 // 1.5*2^23
    const float SQL2E     = 1.2011224087864498f;         // sqrt(log2 e)
    const float L2E       = 1.4426950408889634f;
    const float NQL2E     = -0.25f * 1.4426950408889634f;
    const float BETA      = 0.60653065971263342f;        // e^-1/2
    const float BETA2     = 0.36787944117144233f;        // e^-1

    float dx = xi - sx[j];
    float dy = yi - sy[j];
    float dz = zi - sz[j];
    float dd = fmaf(dx, dx, fmaf(dy, dy, fmaf(dz, dz, 1e-8f)));
    float d;  asm("sqrt.approx.f32 %0, %1;" : "=f"(d) : "f"(dd));
    d = fminf(d, 16.0f);

    float t  = d * INV_DELTA;                      // d/delta in [0, 65.4]
    float hf = fmaf(t, 0.5f, -3.5f);               // (t-7)/2
    float hr = __fadd_rn(__fadd_rn(hf, MAGIC), -MAGIC);   // rint
    hr = fminf(fmaxf(hr, 0.0f), 18.0f);            // kk0 in [0,18], k0 = 2*hr
    kk0 = (int)hr;
    float x0 = fmaf(t, 0.5f, -hr);                 // (d - k0*delta)/w

    // rr0 = exp(-x0^2); g0 = exp(x0 - 1/4)
    float u  = x0 * SQL2E;
    float a0 = -(u * u);
    float rr0; asm("ex2.approx.f32 %0, %1;" : "=f"(rr0) : "f"(a0));
    float ga = fmaf(x0, L2E, NQL2E);
    float g0; asm("ex2.approx.f32 %0, %1;" : "=f"(g0) : "f"(ga));

    float g0sq = g0 * g0;
    float gA   = g0sq * BETA;        // g0*g1
    float gB   = gA * BETA2;         // g1*g2
    Gp  = pack2(gA, gB);
    rrp = pack2(rr0, rr0 * g0);      // (rbf_0, rbf_1)
}

__global__ __launch_bounds__(THREADS)
void rbf_embed_kernel(const int* __restrict__ an,
                      const float* __restrict__ pos,
                      const float* __restrict__ tok,
                      const float* __restrict__ W,
                      const float* __restrict__ bias,
                      float* __restrict__ out)
{
    __shared__ float sx[512], sy[512], sz[512];
    __shared__ ull  sacc2[KK][THREADS];   // 25.6 KB, [kk][thread]
    __shared__ ull  rbfm2[NS][R / 2];     // rbf means, float2 over ii-pairs
    __shared__ int  an_s[R];

    const int tid = threadIdx.x;
    const int b   = blockIdx.y;
    const int i0  = blockIdx.x * R;

    // ---- positions -> smem (SoA) ----
    const float* pb = pos + (size_t)b * 512 * 3;
    for (int j = tid; j < 512; j += THREADS) {
        sx[j] = pb[j * 3 + 0];
        sy[j] = pb[j * 3 + 1];
        sz[j] = pb[j * 3 + 2];
    }
    if (tid < R) an_s[tid] = an[b * 512 + i0 + tid];
    #pragma unroll
    for (int kk = 0; kk < KK; ++kk) sacc2[kk][tid] = 0ULL;
    __syncthreads();

    const int r  = tid & (R - 1);
    const int jg = tid >> 4;
    const float xi = sx[i0 + r], yi = sy[i0 + r], zi = sz[i0 + r];

    const ull B4 = pack2(0.13533528323661270f, 0.13533528323661270f); // e^-2

    const int jbase = jg * JLEN;

    // ---- explicit 2-stage software pipeline over j ----
    int kk0; ull rrp, Gp;
    pair_params(xi, yi, zi, sx, sy, sz, jbase, kk0, rrp, Gp);

    #pragma unroll 2
    for (int jj = 0; jj < JLEN - 1; ++jj) {
        // stage A: params for next j (sqrt + ex2 latency hidden under stage B)
        int kk0n; ull rrpn, Gpn;
        pair_params(xi, yi, zi, sx, sy, sz, jbase + jj + 1, kk0n, rrpn, Gpn);

        // stage B: window RMW for current j
        ull* ap = &sacc2[kk0][tid];
        #pragma unroll
        for (int tt = 0; tt < WIN2; ++tt) {
            ap[tt * THREADS] = add2(ap[tt * THREADS], rrp);
            rrp = mul2(rrp, Gp);
            Gp  = mul2(Gp, B4);
        }

        kk0 = kk0n; rrp = rrpn; Gp = Gpn;
    }
    {   // drain last j
        ull* ap = &sacc2[kk0][tid];
        #pragma unroll
        for (int tt = 0; tt < WIN2; ++tt) {
            ap[tt * THREADS] = add2(ap[tt * THREADS], rrp);
            rrp = mul2(rrp, Gp);
            Gp  = mul2(Gp, B4);
        }
    }
    __syncthreads();

    // ---- reduce JG partials per (k, ii), fold in 1/N ----
    for (int idx = tid; idx < NS * R; idx += THREADS) {
        const int k  = idx >> 4;
        const int ii = idx & (R - 1);
        const float* sf = (const float*)&sacc2[k >> 1][0];
        const int par = (k & 1);
        float s = 0.0f;
        #pragma unroll
        for (int g = 0; g < JG; ++g)
            s += sf[(g * R + ii) * 2 + par];
        ((float*)rbfm2)[k * R + ii] = s * (1.0f / 512.0f);
    }
    __syncthreads();

    // ---- epilogue: [16 x 50] @ [50 x 256] + bias + token gather ----
    {
        const int d0 = tid;
        const float bd0 = __ldg(&bias[d0]);
        const float bd1 = __ldg(&bias[d0 + 128]);
        ull accA[8], accB[8];
        #pragma unroll
        for (int p = 0; p < 8; ++p) {
            const int ta = an_s[2 * p] * 256, tb = an_s[2 * p + 1] * 256;
            accA[p] = pack2(bd0 + __ldg(&tok[ta + d0]),       bd0 + __ldg(&tok[tb + d0]));
            accB[p] = pack2(bd1 + __ldg(&tok[ta + d0 + 128]), bd1 + __ldg(&tok[tb + d0 + 128]));
        }
        #pragma unroll 2
        for (int k = 0; k < NS; ++k) {
            const float wa = __ldg(&W[k * 256 + d0]);
            const float wb = __ldg(&W[k * 256 + d0 + 128]);
            const ull wpa = pack2(wa, wa);
            const ull wpb = pack2(wb, wb);
            const ull* rp = rbfm2[k];
            #pragma unroll
            for (int p = 0; p < 8; ++p) {
                const ull rv = rp[p];      // warp-uniform broadcast LDS.64
                accA[p] = fma2(rv, wpa, accA[p]);
                accB[p] = fma2(rv, wpb, accB[p]);
            }
        }
        float* op = out + ((size_t)(b * 512 + i0)) * 256 + d0;
        #pragma unroll
        for (int p = 0; p < 8; ++p) {
            float lo, hi;
            unpack2(accA[p], lo, hi);
            op[(2 * p) * 256]       = lo;
            op[(2 * p + 1) * 256]   = hi;
            unpack2(accB[p], lo, hi);
            op[(2 * p) * 256 + 128]     = lo;
            op[(2 * p + 1) * 256 + 128] = hi;
        }
    }
}

extern "C" void kernel_launch(void* const* d_in, const int* in_sizes, int n_in,
                              void* d_out, int out_size)
{
    const int*   an   = (const int*)  d_in[0];   // [B,512] int32
    const float* pos  = (const float*)d_in[1];   // [B,512,3] f32
    const float* tok  = (const float*)d_in[2];   // [100,256] f32
    const float* W    = (const float*)d_in[3];   // [50,256]  f32
    const float* bias = (const float*)d_in[4];   // [256]     f32

    const int B = in_sizes[0] / 512;             // 16
    dim3 grid(512 / R, B);
    rbf_embed_kernel<<<grid, THREADS>>>(an, pos, tok, W, bias, (float*)d_out);
}